// round 1
// baseline (speedup 1.0000x reference)
#include <cuda_runtime.h>
#include <math.h>

#define N_NODES 50000
#define N_EDGES 800000
#define H 128
#define G_RBF 50
#define NBINS 7
#define CUTOFF 6.0f
#define SSP_SHIFT 0.6931471805599453f
#define PI_F 3.14159265358979323846f

// ---------------- scratch (no allocation allowed) ----------------
__device__ float g_v[N_NODES * H];
__device__ float g_vlin[N_NODES * H];
__device__ float g_agg[N_NODES * H];
__device__ float g_hbuf[N_NODES * H];
__device__ float g_wtab[2 * NBINS * H];

__device__ __forceinline__ float sspf(float x) {
    // jax softplus = max(x,0)+log1p(exp(-|x|)); minus log(2)
    return fmaxf(x, 0.0f) + log1pf(expf(-fabsf(x))) - SSP_SHIFT;
}

// ---------------- filter table: T[layer][tbin][h] ----------------
// W_filter depends only on trunc(dist) in {0..6} -> 7 rows per layer.
__global__ void table_kernel(const float* __restrict__ m0w0, const float* __restrict__ m0b0,
                             const float* __restrict__ m2w0, const float* __restrict__ m2b0,
                             const float* __restrict__ m0w1, const float* __restrict__ m0b1,
                             const float* __restrict__ m2w1, const float* __restrict__ m2b1,
                             float* __restrict__ wtab) {
    int l = blockIdx.x / NBINS;
    int t = blockIdx.x % NBINS;
    const float* m0w = l ? m0w1 : m0w0;
    const float* m0b = l ? m0b1 : m0b0;
    const float* m2w = l ? m2w1 : m2w0;
    const float* m2b = l ? m2b1 : m2b0;

    __shared__ float hs[H];
    int h = threadIdx.x;

    const float step = CUTOFF / (float)(G_RBF - 1);
    const float coeff = -0.5f / (step * step);
    float acc = m0b[h];
#pragma unroll 10
    for (int g = 0; g < G_RBF; g++) {
        float off = step * (float)g;
        float dd = (float)t - off;
        acc += expf(coeff * dd * dd) * m0w[g * H + h];
    }
    hs[h] = sspf(acc);
    __syncthreads();

    float o = m2b[h];
#pragma unroll 16
    for (int k = 0; k < H; k++) o += hs[k] * m2w[k * H + h];
    wtab[(l * NBINS + t) * H + h] = o;
}

// ---------------- init: v = z @ init_w + init_b ----------------
__global__ void init_kernel(const float* __restrict__ z, const float* __restrict__ iw,
                            const float* __restrict__ ib, float* __restrict__ v) {
    int g = blockIdx.x * blockDim.x + threadIdx.x;
    if (g >= N_NODES * 32) return;
    int n = g >> 5, c4 = g & 31;
    float4 b = ((const float4*)ib)[c4];
    float z0 = z[n * 3 + 0], z1 = z[n * 3 + 1], z2 = z[n * 3 + 2];
    float4 w0 = ((const float4*)iw)[c4];
    float4 w1 = ((const float4*)iw)[32 + c4];
    float4 w2 = ((const float4*)iw)[64 + c4];
    float4 o;
    o.x = b.x + z0 * w0.x + z1 * w1.x + z2 * w2.x;
    o.y = b.y + z0 * w0.y + z1 * w1.y + z2 * w2.y;
    o.z = b.z + z0 * w0.z + z1 * w1.z + z2 * w2.z;
    o.w = b.w + z0 * w0.w + z1 * w1.w + z2 * w2.w;
    ((float4*)v)[n * 32 + c4] = o;
}

// ---------------- zero scratch ----------------
__global__ void zero_kernel(float4* __restrict__ p, int n4) {
    int g = blockIdx.x * blockDim.x + threadIdx.x;
    if (g < n4) p[g] = make_float4(0.f, 0.f, 0.f, 0.f);
}

// ---------------- GEMM: out = [ssp](A @ W [+ bias]) [+ res] ----------------
// A:[n,128], W:[128,128] row-major, per-block tile: 64 nodes x 128 cols,
// 256 threads = 16(tx: 8 cols) x 16(ty: 4 nodes).
template <bool BIAS, bool DOSSP, bool RES>
__global__ void __launch_bounds__(256) gemm128(const float* __restrict__ A,
                                               const float* __restrict__ W,
                                               const float* __restrict__ bias,
                                               const float* __restrict__ res,
                                               float* __restrict__ out, int n) {
    extern __shared__ float sm[];
    float* Ws = sm;              // 128*128
    float* As = sm + H * H;      // 64*129 (padded)
    __shared__ float bs[H];

    int tid = threadIdx.x;
    for (int idx = tid; idx < (H * H) / 4; idx += 256)
        ((float4*)Ws)[idx] = ((const float4*)W)[idx];
    if (BIAS && tid < H) bs[tid] = bias[tid];

    int nb = blockIdx.x * 64;
    for (int idx = tid; idx < 64 * 32; idx += 256) {
        int r = idx >> 5, c4 = idx & 31;
        int gn = nb + r;
        float4 val = (gn < n) ? ((const float4*)A)[gn * 32 + c4]
                              : make_float4(0.f, 0.f, 0.f, 0.f);
        float* dst = &As[r * 129 + c4 * 4];
        dst[0] = val.x; dst[1] = val.y; dst[2] = val.z; dst[3] = val.w;
    }
    __syncthreads();

    int tx = tid & 15, ty = tid >> 4;
    float acc[4][8];
#pragma unroll
    for (int i = 0; i < 4; i++)
#pragma unroll
        for (int jj = 0; jj < 8; jj++) acc[i][jj] = 0.f;

    const float4* Ws4 = (const float4*)Ws;
#pragma unroll 16
    for (int k = 0; k < H; k++) {
        float av[4];
#pragma unroll
        for (int i = 0; i < 4; i++) av[i] = As[(ty * 4 + i) * 129 + k];
        float4 w0 = Ws4[k * 32 + tx * 2];
        float4 w1 = Ws4[k * 32 + tx * 2 + 1];
#pragma unroll
        for (int i = 0; i < 4; i++) {
            acc[i][0] += av[i] * w0.x;
            acc[i][1] += av[i] * w0.y;
            acc[i][2] += av[i] * w0.z;
            acc[i][3] += av[i] * w0.w;
            acc[i][4] += av[i] * w1.x;
            acc[i][5] += av[i] * w1.y;
            acc[i][6] += av[i] * w1.z;
            acc[i][7] += av[i] * w1.w;
        }
    }

#pragma unroll
    for (int i = 0; i < 4; i++) {
        int gn = nb + ty * 4 + i;
        if (gn >= n) continue;
        int cb = tx * 8;
        float4 r0, r1;
        if (RES) {
            r0 = ((const float4*)res)[gn * 32 + tx * 2];
            r1 = ((const float4*)res)[gn * 32 + tx * 2 + 1];
        }
        float v[8];
#pragma unroll
        for (int jj = 0; jj < 8; jj++) {
            float x = acc[i][jj];
            if (BIAS) x += bs[cb + jj];
            if (DOSSP) x = sspf(x);
            v[jj] = x;
        }
        if (RES) {
            v[0] += r0.x; v[1] += r0.y; v[2] += r0.z; v[3] += r0.w;
            v[4] += r1.x; v[5] += r1.y; v[6] += r1.z; v[7] += r1.w;
        }
        float4 o0 = make_float4(v[0], v[1], v[2], v[3]);
        float4 o1 = make_float4(v[4], v[5], v[6], v[7]);
        ((float4*)out)[gn * 32 + tx * 2] = o0;
        ((float4*)out)[gn * 32 + tx * 2 + 1] = o1;
    }
}

// ---------------- edge kernel: agg[i] += vlin[j] * T[tbin] * C ----------------
// one warp per edge, float4 per lane, vector red for the scatter
__global__ void __launch_bounds__(256) edge_kernel(const float* __restrict__ vlin,
                                                   const float* __restrict__ dist,
                                                   const int* __restrict__ ei,
                                                   const float* __restrict__ wtab,
                                                   float* __restrict__ agg) {
    int g = blockIdx.x * 256 + threadIdx.x;
    int e = g >> 5;
    if (e >= N_EDGES) return;
    int lane = g & 31;

    int j = __ldg(ei + e);            // source
    int i = __ldg(ei + N_EDGES + e);  // target
    float d = __ldg(dist + e);
    float C = 0.5f * cosf(d * (PI_F / CUTOFF)) + 0.5f;
    int tb = (int)d;
    if (tb > NBINS - 1) tb = NBINS - 1;

    float4 w = ((const float4*)wtab)[tb * 32 + lane];
    float4 x = __ldg(((const float4*)vlin) + (size_t)j * 32 + lane);
    float4 vv;
    vv.x = x.x * w.x * C;
    vv.y = x.y * w.y * C;
    vv.z = x.z * w.z * C;
    vv.w = x.w * w.w * C;

    float* dst = agg + (size_t)i * H + lane * 4;
    asm volatile("red.global.add.v4.f32 [%0], {%1, %2, %3, %4};"
                 :: "l"(dst), "f"(vv.x), "f"(vv.y), "f"(vv.z), "f"(vv.w)
                 : "memory");
}

// ---------------- readout: out = hbuf @ u_l2_w + u_l2_b ----------------
// warp per node, shuffle reduce
__global__ void __launch_bounds__(256) readout_kernel(const float* __restrict__ hbuf,
                                                      const float* __restrict__ w2,
                                                      const float* __restrict__ b2,
                                                      float* __restrict__ out) {
    __shared__ float ws[H * 3];
    int tid = threadIdx.x;
    for (int idx = tid; idx < H * 3; idx += 256) ws[idx] = w2[idx];
    __syncthreads();

    int g = blockIdx.x * 256 + tid;
    int node = g >> 5;
    if (node >= N_NODES) return;
    int lane = g & 31;

    float4 h = ((const float4*)hbuf)[node * 32 + lane];
    int k0 = lane * 4;
    float s0 = h.x * ws[k0 * 3 + 0] + h.y * ws[(k0 + 1) * 3 + 0] +
               h.z * ws[(k0 + 2) * 3 + 0] + h.w * ws[(k0 + 3) * 3 + 0];
    float s1 = h.x * ws[k0 * 3 + 1] + h.y * ws[(k0 + 1) * 3 + 1] +
               h.z * ws[(k0 + 2) * 3 + 1] + h.w * ws[(k0 + 3) * 3 + 1];
    float s2 = h.x * ws[k0 * 3 + 2] + h.y * ws[(k0 + 1) * 3 + 2] +
               h.z * ws[(k0 + 2) * 3 + 2] + h.w * ws[(k0 + 3) * 3 + 2];
#pragma unroll
    for (int off = 16; off; off >>= 1) {
        s0 += __shfl_down_sync(0xffffffffu, s0, off);
        s1 += __shfl_down_sync(0xffffffffu, s1, off);
        s2 += __shfl_down_sync(0xffffffffu, s2, off);
    }
    if (lane == 0) {
        out[node * 3 + 0] = s0 + b2[0];
        out[node * 3 + 1] = s1 + b2[1];
        out[node * 3 + 2] = s2 + b2[2];
    }
}

// ---------------- launch ----------------
static const int GEMM_SMEM = (H * H + 64 * 129) * sizeof(float);

extern "C" void kernel_launch(void* const* d_in, const int* in_sizes, int n_in,
                              void* d_out, int out_size) {
    const float* z        = (const float*)d_in[0];
    const float* dist     = (const float*)d_in[1];
    const int*   ei       = (const int*)d_in[2];
    const float* init_w   = (const float*)d_in[3];
    const float* init_b   = (const float*)d_in[4];
    const float* e_lin_w[2] = {(const float*)d_in[5],  (const float*)d_in[14]};
    const float* e_m0_w[2]  = {(const float*)d_in[6],  (const float*)d_in[15]};
    const float* e_m0_b[2]  = {(const float*)d_in[7],  (const float*)d_in[16]};
    const float* e_m2_w[2]  = {(const float*)d_in[8],  (const float*)d_in[17]};
    const float* e_m2_b[2]  = {(const float*)d_in[9],  (const float*)d_in[18]};
    const float* v_l1_w[2]  = {(const float*)d_in[10], (const float*)d_in[19]};
    const float* v_l1_b[2]  = {(const float*)d_in[11], (const float*)d_in[20]};
    const float* v_l2_w[2]  = {(const float*)d_in[12], (const float*)d_in[21]};
    const float* v_l2_b[2]  = {(const float*)d_in[13], (const float*)d_in[22]};
    const float* u_l1_w   = (const float*)d_in[23];
    const float* u_l1_b   = (const float*)d_in[24];
    const float* u_l2_w   = (const float*)d_in[25];
    const float* u_l2_b   = (const float*)d_in[26];
    float* out = (float*)d_out;

    float *v, *vlin, *agg, *hbuf, *wtab;
    cudaGetSymbolAddress((void**)&v,    g_v);
    cudaGetSymbolAddress((void**)&vlin, g_vlin);
    cudaGetSymbolAddress((void**)&agg,  g_agg);
    cudaGetSymbolAddress((void**)&hbuf, g_hbuf);
    cudaGetSymbolAddress((void**)&wtab, g_wtab);

    cudaFuncSetAttribute((const void*)gemm128<false, false, false>,
                         cudaFuncAttributeMaxDynamicSharedMemorySize, GEMM_SMEM);
    cudaFuncSetAttribute((const void*)gemm128<true, true, false>,
                         cudaFuncAttributeMaxDynamicSharedMemorySize, GEMM_SMEM);
    cudaFuncSetAttribute((const void*)gemm128<true, false, true>,
                         cudaFuncAttributeMaxDynamicSharedMemorySize, GEMM_SMEM);

    const int gemm_grid = (N_NODES + 63) / 64;
    const int nh4 = N_NODES * H / 4;

    table_kernel<<<2 * NBINS, H>>>(e_m0_w[0], e_m0_b[0], e_m2_w[0], e_m2_b[0],
                                   e_m0_w[1], e_m0_b[1], e_m2_w[1], e_m2_b[1], wtab);
    init_kernel<<<(N_NODES * 32 + 255) / 256, 256>>>(z, init_w, init_b, v);

    for (int l = 0; l < 2; l++) {
        gemm128<false, false, false><<<gemm_grid, 256, GEMM_SMEM>>>(
            v, e_lin_w[l], nullptr, nullptr, vlin, N_NODES);
        zero_kernel<<<(nh4 + 255) / 256, 256>>>((float4*)agg, nh4);
        edge_kernel<<<(N_EDGES * 32 + 255) / 256, 256>>>(
            vlin, dist, ei, wtab + l * NBINS * H, agg);
        gemm128<true, true, false><<<gemm_grid, 256, GEMM_SMEM>>>(
            agg, v_l1_w[l], v_l1_b[l], nullptr, hbuf, N_NODES);
        gemm128<true, false, true><<<gemm_grid, 256, GEMM_SMEM>>>(
            hbuf, v_l2_w[l], v_l2_b[l], v, v, N_NODES);
    }

    gemm128<true, true, false><<<gemm_grid, 256, GEMM_SMEM>>>(
        v, u_l1_w, u_l1_b, nullptr, hbuf, N_NODES);
    readout_kernel<<<(N_NODES * 32 + 255) / 256, 256>>>(hbuf, u_l2_w, u_l2_b, out);
}

// round 2
// speedup vs baseline: 1.1091x; 1.1091x over previous
#include <cuda_runtime.h>
#include <math.h>

#define N_NODES 50000
#define N_EDGES 800000
#define H 128
#define G_RBF 50
#define NBINS 7
#define CUTOFF 6.0f
#define SSP_SHIFT 0.6931471805599453f
#define PI_F 3.14159265358979323846f

#define SCAN_BLOCKS ((N_NODES + 255) / 256)   // 196

// ---------------- scratch (no allocation allowed) ----------------
__device__ float g_v[N_NODES * H];
__device__ float g_vlin[N_NODES * H];
__device__ float g_agg[N_NODES * H];
__device__ float g_hbuf[N_NODES * H];
__device__ float g_wtab[2 * NBINS * H];
// CSR scratch
__device__ int   g_cnt[N_NODES];
__device__ int   g_off[N_NODES + 1];
__device__ int   g_pos[N_NODES];
__device__ int   g_bsum[SCAN_BLOCKS];
__device__ int   g_jt[N_EDGES];     // j | (tbin << 27)
__device__ float g_cs[N_EDGES];     // cutoff gate C

__device__ __forceinline__ float sspf(float x) {
    return fmaxf(x, 0.0f) + log1pf(expf(-fabsf(x))) - SSP_SHIFT;
}

// ---------------- filter table: T[layer][tbin][h] ----------------
__global__ void table_kernel(const float* __restrict__ m0w0, const float* __restrict__ m0b0,
                             const float* __restrict__ m2w0, const float* __restrict__ m2b0,
                             const float* __restrict__ m0w1, const float* __restrict__ m0b1,
                             const float* __restrict__ m2w1, const float* __restrict__ m2b1,
                             float* __restrict__ wtab) {
    int l = blockIdx.x / NBINS;
    int t = blockIdx.x % NBINS;
    const float* m0w = l ? m0w1 : m0w0;
    const float* m0b = l ? m0b1 : m0b0;
    const float* m2w = l ? m2w1 : m2w0;
    const float* m2b = l ? m2b1 : m2b0;

    __shared__ float hs[H];
    int h = threadIdx.x;

    const float step = CUTOFF / (float)(G_RBF - 1);
    const float coeff = -0.5f / (step * step);
    float acc = m0b[h];
#pragma unroll 10
    for (int g = 0; g < G_RBF; g++) {
        float off = step * (float)g;
        float dd = (float)t - off;
        acc += expf(coeff * dd * dd) * m0w[g * H + h];
    }
    hs[h] = sspf(acc);
    __syncthreads();

    float o = m2b[h];
#pragma unroll 16
    for (int k = 0; k < H; k++) o += hs[k] * m2w[k * H + h];
    wtab[(l * NBINS + t) * H + h] = o;
}

// ---------------- init: v = z @ init_w + init_b ----------------
__global__ void init_kernel(const float* __restrict__ z, const float* __restrict__ iw,
                            const float* __restrict__ ib, float* __restrict__ v) {
    int g = blockIdx.x * blockDim.x + threadIdx.x;
    if (g >= N_NODES * 32) return;
    int n = g >> 5, c4 = g & 31;
    float4 b = ((const float4*)ib)[c4];
    float z0 = z[n * 3 + 0], z1 = z[n * 3 + 1], z2 = z[n * 3 + 2];
    float4 w0 = ((const float4*)iw)[c4];
    float4 w1 = ((const float4*)iw)[32 + c4];
    float4 w2 = ((const float4*)iw)[64 + c4];
    float4 o;
    o.x = b.x + z0 * w0.x + z1 * w1.x + z2 * w2.x;
    o.y = b.y + z0 * w0.y + z1 * w1.y + z2 * w2.y;
    o.z = b.z + z0 * w0.z + z1 * w1.z + z2 * w2.z;
    o.w = b.w + z0 * w0.w + z1 * w1.w + z2 * w2.w;
    ((float4*)v)[n * 32 + c4] = o;
}

// ---------------- CSR build ----------------
__global__ void zero_cnt_kernel(int* __restrict__ cnt) {
    int i = blockIdx.x * blockDim.x + threadIdx.x;
    if (i < N_NODES) cnt[i] = 0;
}

__global__ void hist_kernel(const int* __restrict__ ei, int* __restrict__ cnt) {
    int e = blockIdx.x * blockDim.x + threadIdx.x;
    if (e < N_EDGES) atomicAdd(&cnt[ei[N_EDGES + e]], 1);
}

__global__ void scan1_kernel(const int* __restrict__ cnt, int* __restrict__ off,
                             int* __restrict__ bsum) {
    __shared__ int s[256];
    int t = threadIdx.x;
    int i = blockIdx.x * 256 + t;
    int v = (i < N_NODES) ? cnt[i] : 0;
    s[t] = v;
    __syncthreads();
#pragma unroll
    for (int o = 1; o < 256; o <<= 1) {
        int x = (t >= o) ? s[t - o] : 0;
        __syncthreads();
        s[t] += x;
        __syncthreads();
    }
    if (i < N_NODES) off[i] = s[t] - v;  // exclusive within block
    if (t == 255) bsum[blockIdx.x] = s[255];
}

__global__ void scan2_kernel(int* __restrict__ bsum) {
    __shared__ int s[256];
    int t = threadIdx.x;
    int v = (t < SCAN_BLOCKS) ? bsum[t] : 0;
    s[t] = v;
    __syncthreads();
#pragma unroll
    for (int o = 1; o < 256; o <<= 1) {
        int x = (t >= o) ? s[t - o] : 0;
        __syncthreads();
        s[t] += x;
        __syncthreads();
    }
    if (t < SCAN_BLOCKS) bsum[t] = s[t] - v;  // exclusive
}

__global__ void scan3_kernel(int* __restrict__ off, const int* __restrict__ bsum,
                             int* __restrict__ pos) {
    int i = blockIdx.x * blockDim.x + threadIdx.x;
    if (i < N_NODES) {
        int o = off[i] + bsum[i >> 8];
        off[i] = o;
        pos[i] = o;
    }
    if (i == 0) off[N_NODES] = N_EDGES;
}

__global__ void scatter_kernel(const int* __restrict__ ei, const float* __restrict__ dist,
                               int* __restrict__ pos, int* __restrict__ jt,
                               float* __restrict__ cs) {
    int e = blockIdx.x * blockDim.x + threadIdx.x;
    if (e >= N_EDGES) return;
    int j = ei[e];
    int i = ei[N_EDGES + e];
    float d = dist[e];
    int tb = (int)d;
    if (tb > NBINS - 1) tb = NBINS - 1;
    float C = 0.5f * cosf(d * (PI_F / CUTOFF)) + 0.5f;
    int p = atomicAdd(&pos[i], 1);
    jt[p] = j | (tb << 27);
    cs[p] = C;
}

// ---------------- aggregate: agg[i] = sum_{e->i} vlin[j]*T[tb]*C ----------------
// warp per node, no atomics
__global__ void __launch_bounds__(256) agg_kernel(const float* __restrict__ vlin,
                                                  const int* __restrict__ off,
                                                  const int* __restrict__ jt,
                                                  const float* __restrict__ cs,
                                                  const float* __restrict__ wtab,
                                                  float* __restrict__ agg) {
    __shared__ float4 ws[NBINS * 32];
    int tid = threadIdx.x;
    if (tid < NBINS * 32) ws[tid] = ((const float4*)wtab)[tid];
    __syncthreads();

    int node = blockIdx.x * 8 + (tid >> 5);
    if (node >= N_NODES) return;
    int lane = tid & 31;

    int s = off[node], e = off[node + 1];
    float4 acc = make_float4(0.f, 0.f, 0.f, 0.f);
    const float4* vlin4 = (const float4*)vlin;

    for (int base = s; base < e; base += 32) {
        int m = min(32, e - base);
        int mj = (lane < m) ? jt[base + lane] : 0;
        float mc = (lane < m) ? cs[base + lane] : 0.f;
        for (int t = 0; t < m; t++) {
            int jv = __shfl_sync(0xffffffffu, mj, t);
            float c = __shfl_sync(0xffffffffu, mc, t);
            int j = jv & 0x07FFFFFF;
            int tb = jv >> 27;
            float4 x = __ldg(vlin4 + (size_t)j * 32 + lane);
            float4 w = ws[tb * 32 + lane];
            acc.x += x.x * w.x * c;
            acc.y += x.y * w.y * c;
            acc.z += x.z * w.z * c;
            acc.w += x.w * w.w * c;
        }
    }
    ((float4*)agg)[(size_t)node * 32 + lane] = acc;
}

// ---------------- GEMM: out = [ssp](A @ W [+ bias]) [+ res] ----------------
// A:[n,128], W:[128,128] row-major. Tile: 64 nodes x 128 cols, 256 threads.
// A staged TRANSPOSED in smem (k-major) so the inner loop is 3x LDS.128 per k.
#define AT_STRIDE 68  // floats per k-row (64 + pad), 16B-aligned rows
template <bool BIAS, bool DOSSP, bool RES>
__global__ void __launch_bounds__(256) gemm128(const float* __restrict__ A,
                                               const float* __restrict__ W,
                                               const float* __restrict__ bias,
                                               const float* __restrict__ res,
                                               float* __restrict__ out, int n) {
    extern __shared__ float sm[];
    float* Ws = sm;                 // 128*128
    float* At = sm + H * H;         // 128 x AT_STRIDE (k-major)
    __shared__ float bs[H];

    int tid = threadIdx.x;
    for (int idx = tid; idx < (H * H) / 4; idx += 256)
        ((float4*)Ws)[idx] = ((const float4*)W)[idx];
    if (BIAS && tid < H) bs[tid] = bias[tid];

    int nb = blockIdx.x * 64;
    // load A tile [64 nodes x 128] and store transposed: At[k][node]
    for (int idx = tid; idx < 64 * 32; idx += 256) {
        int r = idx & 63;       // node within tile
        int c = idx >> 6;       // float4 column group (k = 4c..4c+3)
        int gn = nb + r;
        float4 val = (gn < n) ? ((const float4*)A)[(size_t)gn * 32 + c]
                              : make_float4(0.f, 0.f, 0.f, 0.f);
        At[(4 * c + 0) * AT_STRIDE + r] = val.x;
        At[(4 * c + 1) * AT_STRIDE + r] = val.y;
        At[(4 * c + 2) * AT_STRIDE + r] = val.z;
        At[(4 * c + 3) * AT_STRIDE + r] = val.w;
    }
    __syncthreads();

    int tx = tid & 15, ty = tid >> 4;   // tx: 8-col group, ty: 4-node group
    float acc[4][8];
#pragma unroll
    for (int i = 0; i < 4; i++)
#pragma unroll
        for (int jj = 0; jj < 8; jj++) acc[i][jj] = 0.f;

    const float4* Ws4 = (const float4*)Ws;
    const float4* At4 = (const float4*)At;
#pragma unroll 16
    for (int k = 0; k < H; k++) {
        float4 a4 = At4[k * (AT_STRIDE / 4) + ty];
        float4 w0 = Ws4[k * 32 + tx * 2];
        float4 w1 = Ws4[k * 32 + tx * 2 + 1];
        float av[4] = {a4.x, a4.y, a4.z, a4.w};
#pragma unroll
        for (int i = 0; i < 4; i++) {
            acc[i][0] += av[i] * w0.x;
            acc[i][1] += av[i] * w0.y;
            acc[i][2] += av[i] * w0.z;
            acc[i][3] += av[i] * w0.w;
            acc[i][4] += av[i] * w1.x;
            acc[i][5] += av[i] * w1.y;
            acc[i][6] += av[i] * w1.z;
            acc[i][7] += av[i] * w1.w;
        }
    }

#pragma unroll
    for (int i = 0; i < 4; i++) {
        int gn = nb + ty * 4 + i;
        if (gn >= n) continue;
        int cb = tx * 8;
        float4 r0, r1;
        if (RES) {
            r0 = ((const float4*)res)[(size_t)gn * 32 + tx * 2];
            r1 = ((const float4*)res)[(size_t)gn * 32 + tx * 2 + 1];
        }
        float v[8];
#pragma unroll
        for (int jj = 0; jj < 8; jj++) {
            float x = acc[i][jj];
            if (BIAS) x += bs[cb + jj];
            if (DOSSP) x = sspf(x);
            v[jj] = x;
        }
        if (RES) {
            v[0] += r0.x; v[1] += r0.y; v[2] += r0.z; v[3] += r0.w;
            v[4] += r1.x; v[5] += r1.y; v[6] += r1.z; v[7] += r1.w;
        }
        ((float4*)out)[(size_t)gn * 32 + tx * 2]     = make_float4(v[0], v[1], v[2], v[3]);
        ((float4*)out)[(size_t)gn * 32 + tx * 2 + 1] = make_float4(v[4], v[5], v[6], v[7]);
    }
}

// ---------------- readout: out = hbuf @ u_l2_w + u_l2_b ----------------
__global__ void __launch_bounds__(256) readout_kernel(const float* __restrict__ hbuf,
                                                      const float* __restrict__ w2,
                                                      const float* __restrict__ b2,
                                                      float* __restrict__ out) {
    __shared__ float ws[H * 3];
    int tid = threadIdx.x;
    for (int idx = tid; idx < H * 3; idx += 256) ws[idx] = w2[idx];
    __syncthreads();

    int g = blockIdx.x * 256 + tid;
    int node = g >> 5;
    if (node >= N_NODES) return;
    int lane = g & 31;

    float4 h = ((const float4*)hbuf)[node * 32 + lane];
    int k0 = lane * 4;
    float s0 = h.x * ws[k0 * 3 + 0] + h.y * ws[(k0 + 1) * 3 + 0] +
               h.z * ws[(k0 + 2) * 3 + 0] + h.w * ws[(k0 + 3) * 3 + 0];
    float s1 = h.x * ws[k0 * 3 + 1] + h.y * ws[(k0 + 1) * 3 + 1] +
               h.z * ws[(k0 + 2) * 3 + 1] + h.w * ws[(k0 + 3) * 3 + 1];
    float s2 = h.x * ws[k0 * 3 + 2] + h.y * ws[(k0 + 1) * 3 + 2] +
               h.z * ws[(k0 + 2) * 3 + 2] + h.w * ws[(k0 + 3) * 3 + 2];
#pragma unroll
    for (int off = 16; off; off >>= 1) {
        s0 += __shfl_down_sync(0xffffffffu, s0, off);
        s1 += __shfl_down_sync(0xffffffffu, s1, off);
        s2 += __shfl_down_sync(0xffffffffu, s2, off);
    }
    if (lane == 0) {
        out[node * 3 + 0] = s0 + b2[0];
        out[node * 3 + 1] = s1 + b2[1];
        out[node * 3 + 2] = s2 + b2[2];
    }
}

// ---------------- launch ----------------
static const int GEMM_SMEM = (H * H + H * AT_STRIDE) * sizeof(float);

extern "C" void kernel_launch(void* const* d_in, const int* in_sizes, int n_in,
                              void* d_out, int out_size) {
    const float* z        = (const float*)d_in[0];
    const float* dist     = (const float*)d_in[1];
    const int*   ei       = (const int*)d_in[2];
    const float* init_w   = (const float*)d_in[3];
    const float* init_b   = (const float*)d_in[4];
    const float* e_lin_w[2] = {(const float*)d_in[5],  (const float*)d_in[14]};
    const float* e_m0_w[2]  = {(const float*)d_in[6],  (const float*)d_in[15]};
    const float* e_m0_b[2]  = {(const float*)d_in[7],  (const float*)d_in[16]};
    const float* e_m2_w[2]  = {(const float*)d_in[8],  (const float*)d_in[17]};
    const float* e_m2_b[2]  = {(const float*)d_in[9],  (const float*)d_in[18]};
    const float* v_l1_w[2]  = {(const float*)d_in[10], (const float*)d_in[19]};
    const float* v_l1_b[2]  = {(const float*)d_in[11], (const float*)d_in[20]};
    const float* v_l2_w[2]  = {(const float*)d_in[12], (const float*)d_in[21]};
    const float* v_l2_b[2]  = {(const float*)d_in[13], (const float*)d_in[22]};
    const float* u_l1_w   = (const float*)d_in[23];
    const float* u_l1_b   = (const float*)d_in[24];
    const float* u_l2_w   = (const float*)d_in[25];
    const float* u_l2_b   = (const float*)d_in[26];
    float* out = (float*)d_out;

    float *v, *vlin, *agg, *hbuf, *wtab, *cs;
    int *cnt, *off, *pos, *bsum, *jt;
    cudaGetSymbolAddress((void**)&v,    g_v);
    cudaGetSymbolAddress((void**)&vlin, g_vlin);
    cudaGetSymbolAddress((void**)&agg,  g_agg);
    cudaGetSymbolAddress((void**)&hbuf, g_hbuf);
    cudaGetSymbolAddress((void**)&wtab, g_wtab);
    cudaGetSymbolAddress((void**)&cnt,  g_cnt);
    cudaGetSymbolAddress((void**)&off,  g_off);
    cudaGetSymbolAddress((void**)&pos,  g_pos);
    cudaGetSymbolAddress((void**)&bsum, g_bsum);
    cudaGetSymbolAddress((void**)&jt,   g_jt);
    cudaGetSymbolAddress((void**)&cs,   g_cs);

    cudaFuncSetAttribute((const void*)gemm128<false, false, false>,
                         cudaFuncAttributeMaxDynamicSharedMemorySize, GEMM_SMEM);
    cudaFuncSetAttribute((const void*)gemm128<true, true, false>,
                         cudaFuncAttributeMaxDynamicSharedMemorySize, GEMM_SMEM);
    cudaFuncSetAttribute((const void*)gemm128<true, false, true>,
                         cudaFuncAttributeMaxDynamicSharedMemorySize, GEMM_SMEM);

    const int gemm_grid = (N_NODES + 63) / 64;
    const int egrid = (N_EDGES + 255) / 256;
    const int ngrid = (N_NODES + 255) / 256;

    table_kernel<<<2 * NBINS, H>>>(e_m0_w[0], e_m0_b[0], e_m2_w[0], e_m2_b[0],
                                   e_m0_w[1], e_m0_b[1], e_m2_w[1], e_m2_b[1], wtab);
    init_kernel<<<(N_NODES * 32 + 255) / 256, 256>>>(z, init_w, init_b, v);

    // CSR build (shared by both layers)
    zero_cnt_kernel<<<ngrid, 256>>>(cnt);
    hist_kernel<<<egrid, 256>>>(ei, cnt);
    scan1_kernel<<<SCAN_BLOCKS, 256>>>(cnt, off, bsum);
    scan2_kernel<<<1, 256>>>(bsum);
    scan3_kernel<<<SCAN_BLOCKS, 256>>>(off, bsum, pos);
    scatter_kernel<<<egrid, 256>>>(ei, dist, pos, jt, cs);

    for (int l = 0; l < 2; l++) {
        gemm128<false, false, false><<<gemm_grid, 256, GEMM_SMEM>>>(
            v, e_lin_w[l], nullptr, nullptr, vlin, N_NODES);
        agg_kernel<<<(N_NODES + 7) / 8, 256>>>(vlin, off, jt, cs,
                                               wtab + l * NBINS * H, agg);
        gemm128<true, true, false><<<gemm_grid, 256, GEMM_SMEM>>>(
            agg, v_l1_w[l], v_l1_b[l], nullptr, hbuf, N_NODES);
        gemm128<true, false, true><<<gemm_grid, 256, GEMM_SMEM>>>(
            hbuf, v_l2_w[l], v_l2_b[l], v, v, N_NODES);
    }

    gemm128<true, true, false><<<gemm_grid, 256, GEMM_SMEM>>>(
        v, u_l1_w, u_l1_b, nullptr, hbuf, N_NODES);
    readout_kernel<<<(N_NODES * 32 + 255) / 256, 256>>>(hbuf, u_l2_w, u_l2_b, out);
}

// round 3
// speedup vs baseline: 1.2965x; 1.1689x over previous
#include <cuda_runtime.h>
#include <math.h>

#define N_NODES 50000
#define N_EDGES 800000
#define H 128
#define G_RBF 50
#define NBINS 7
#define CUTOFF 6.0f
#define SSP_SHIFT 0.6931471805599453f
#define PI_F 3.14159265358979323846f

#define SCAN_BLOCKS ((N_NODES + 255) / 256)   // 196
#define AT_STRIDE 132   // 128 + 4 pad (floats), rows stay 16B-aligned

// ---------------- scratch (no allocation allowed) ----------------
__device__ float g_v[N_NODES * H];
__device__ float g_vlin[N_NODES * H];
__device__ float g_agg[N_NODES * H];
__device__ float g_hbuf[N_NODES * H];
__device__ float g_wtab[2 * NBINS * H];
// CSR scratch
__device__ int   g_cnt[N_NODES];
__device__ int   g_off[N_NODES + 1];
__device__ int   g_pos[N_NODES];
__device__ int   g_bsum[SCAN_BLOCKS];
__device__ int   g_jt[N_EDGES];     // j | (tbin << 27)
__device__ float g_cs[N_EDGES];     // cutoff gate C

__device__ __forceinline__ float sspf(float x) {
    return fmaxf(x, 0.0f) + log1pf(expf(-fabsf(x))) - SSP_SHIFT;
}

// ---------------- filter table: T[layer][tbin][h] ----------------
__global__ void table_kernel(const float* __restrict__ m0w0, const float* __restrict__ m0b0,
                             const float* __restrict__ m2w0, const float* __restrict__ m2b0,
                             const float* __restrict__ m0w1, const float* __restrict__ m0b1,
                             const float* __restrict__ m2w1, const float* __restrict__ m2b1,
                             float* __restrict__ wtab) {
    int l = blockIdx.x / NBINS;
    int t = blockIdx.x % NBINS;
    const float* m0w = l ? m0w1 : m0w0;
    const float* m0b = l ? m0b1 : m0b0;
    const float* m2w = l ? m2w1 : m2w0;
    const float* m2b = l ? m2b1 : m2b0;

    __shared__ float hs[H];
    int h = threadIdx.x;

    const float step = CUTOFF / (float)(G_RBF - 1);
    const float coeff = -0.5f / (step * step);
    float acc = m0b[h];
#pragma unroll 10
    for (int g = 0; g < G_RBF; g++) {
        float off = step * (float)g;
        float dd = (float)t - off;
        acc += expf(coeff * dd * dd) * m0w[g * H + h];
    }
    hs[h] = sspf(acc);
    __syncthreads();

    float o = m2b[h];
#pragma unroll 16
    for (int k = 0; k < H; k++) o += hs[k] * m2w[k * H + h];
    wtab[(l * NBINS + t) * H + h] = o;
}

// ---------------- init: v = z @ init_w + init_b ----------------
__global__ void init_kernel(const float* __restrict__ z, const float* __restrict__ iw,
                            const float* __restrict__ ib, float* __restrict__ v) {
    int g = blockIdx.x * blockDim.x + threadIdx.x;
    if (g >= N_NODES * 32) return;
    int n = g >> 5, c4 = g & 31;
    float4 b = ((const float4*)ib)[c4];
    float z0 = z[n * 3 + 0], z1 = z[n * 3 + 1], z2 = z[n * 3 + 2];
    float4 w0 = ((const float4*)iw)[c4];
    float4 w1 = ((const float4*)iw)[32 + c4];
    float4 w2 = ((const float4*)iw)[64 + c4];
    float4 o;
    o.x = b.x + z0 * w0.x + z1 * w1.x + z2 * w2.x;
    o.y = b.y + z0 * w0.y + z1 * w1.y + z2 * w2.y;
    o.z = b.z + z0 * w0.z + z1 * w1.z + z2 * w2.z;
    o.w = b.w + z0 * w0.w + z1 * w1.w + z2 * w2.w;
    ((float4*)v)[n * 32 + c4] = o;
}

// ---------------- CSR build ----------------
__global__ void zero_cnt_kernel(int* __restrict__ cnt) {
    int i = blockIdx.x * blockDim.x + threadIdx.x;
    if (i < N_NODES) cnt[i] = 0;
}

__global__ void hist_kernel(const int* __restrict__ ei, int* __restrict__ cnt) {
    int e = blockIdx.x * blockDim.x + threadIdx.x;
    if (e < N_EDGES) atomicAdd(&cnt[ei[N_EDGES + e]], 1);
}

__global__ void scan1_kernel(const int* __restrict__ cnt, int* __restrict__ off,
                             int* __restrict__ bsum) {
    __shared__ int s[256];
    int t = threadIdx.x;
    int i = blockIdx.x * 256 + t;
    int v = (i < N_NODES) ? cnt[i] : 0;
    s[t] = v;
    __syncthreads();
#pragma unroll
    for (int o = 1; o < 256; o <<= 1) {
        int x = (t >= o) ? s[t - o] : 0;
        __syncthreads();
        s[t] += x;
        __syncthreads();
    }
    if (i < N_NODES) off[i] = s[t] - v;  // exclusive within block
    if (t == 255) bsum[blockIdx.x] = s[255];
}

__global__ void scan2_kernel(int* __restrict__ bsum) {
    __shared__ int s[256];
    int t = threadIdx.x;
    int v = (t < SCAN_BLOCKS) ? bsum[t] : 0;
    s[t] = v;
    __syncthreads();
#pragma unroll
    for (int o = 1; o < 256; o <<= 1) {
        int x = (t >= o) ? s[t - o] : 0;
        __syncthreads();
        s[t] += x;
        __syncthreads();
    }
    if (t < SCAN_BLOCKS) bsum[t] = s[t] - v;  // exclusive
}

__global__ void scan3_kernel(int* __restrict__ off, const int* __restrict__ bsum,
                             int* __restrict__ pos) {
    int i = blockIdx.x * blockDim.x + threadIdx.x;
    if (i < N_NODES) {
        int o = off[i] + bsum[i >> 8];
        off[i] = o;
        pos[i] = o;
    }
    if (i == 0) off[N_NODES] = N_EDGES;
}

__global__ void scatter_kernel(const int* __restrict__ ei, const float* __restrict__ dist,
                               int* __restrict__ pos, int* __restrict__ jt,
                               float* __restrict__ cs) {
    int e = blockIdx.x * blockDim.x + threadIdx.x;
    if (e >= N_EDGES) return;
    int j = ei[e];
    int i = ei[N_EDGES + e];
    float d = dist[e];
    int tb = (int)d;
    if (tb > NBINS - 1) tb = NBINS - 1;
    float C = 0.5f * cosf(d * (PI_F / CUTOFF)) + 0.5f;
    int p = atomicAdd(&pos[i], 1);
    jt[p] = j | (tb << 27);
    cs[p] = C;
}

// ---------------- aggregate: agg[i] = sum_{e->i} vlin[j]*T[tb]*C ----------------
// warp per node, no atomics
__global__ void __launch_bounds__(256) agg_kernel(const float* __restrict__ vlin,
                                                  const int* __restrict__ off,
                                                  const int* __restrict__ jt,
                                                  const float* __restrict__ cs,
                                                  const float* __restrict__ wtab,
                                                  float* __restrict__ agg) {
    __shared__ float4 ws[NBINS * 32];
    int tid = threadIdx.x;
    if (tid < NBINS * 32) ws[tid] = ((const float4*)wtab)[tid];
    __syncthreads();

    int node = blockIdx.x * 8 + (tid >> 5);
    if (node >= N_NODES) return;
    int lane = tid & 31;

    int s = off[node], e = off[node + 1];
    float4 acc = make_float4(0.f, 0.f, 0.f, 0.f);
    const float4* vlin4 = (const float4*)vlin;

    for (int base = s; base < e; base += 32) {
        int m = min(32, e - base);
        int mj = (lane < m) ? jt[base + lane] : 0;
        float mc = (lane < m) ? cs[base + lane] : 0.f;
        for (int t = 0; t < m; t++) {
            int jv = __shfl_sync(0xffffffffu, mj, t);
            float c = __shfl_sync(0xffffffffu, mc, t);
            int j = jv & 0x07FFFFFF;
            int tb = jv >> 27;
            float4 x = __ldg(vlin4 + (size_t)j * 32 + lane);
            float4 w = ws[tb * 32 + lane];
            acc.x += x.x * w.x * c;
            acc.y += x.y * w.y * c;
            acc.z += x.z * w.z * c;
            acc.w += x.w * w.w * c;
        }
    }
    ((float4*)agg)[(size_t)node * 32 + lane] = acc;
}

// ---------------- GEMM: out = [ssp](A @ W [+ bias]) [+ res] ----------------
// A:[n,128], W:[128,128] row-major. Tile: 128 nodes x 128 cols, 256 threads.
// Each thread: 8 nodes x 8 cols, accumulators packed as f32x2 col-pairs,
// inner product via fma.rn.f32x2 (SASS FFMA2, 2x fp32 throughput, same rounding).
template <bool BIAS, bool DOSSP, bool RES>
__global__ void __launch_bounds__(256) gemm128(const float* __restrict__ A,
                                               const float* __restrict__ W,
                                               const float* __restrict__ bias,
                                               const float* __restrict__ res,
                                               float* __restrict__ out, int n) {
    extern __shared__ float sm[];
    float* Ws = sm;                 // 128*128
    float* At = sm + H * H;         // 128 x AT_STRIDE (k-major, node contiguous)
    __shared__ float bs[H];

    int tid = threadIdx.x;
    for (int idx = tid; idx < (H * H) / 4; idx += 256)
        ((float4*)Ws)[idx] = ((const float4*)W)[idx];
    if (BIAS && tid < H) bs[tid] = bias[tid];

    int nb = blockIdx.x * 128;
    // load A tile [128 nodes x 128 k], store transposed: At[k][node]
    for (int idx = tid; idx < 128 * 32; idx += 256) {
        int r = idx & 127;      // node within tile
        int c = idx >> 7;       // float4 column group (k = 4c..4c+3)
        int gn = nb + r;
        float4 val = (gn < n) ? ((const float4*)A)[(size_t)gn * 32 + c]
                              : make_float4(0.f, 0.f, 0.f, 0.f);
        At[(4 * c + 0) * AT_STRIDE + r] = val.x;
        At[(4 * c + 1) * AT_STRIDE + r] = val.y;
        At[(4 * c + 2) * AT_STRIDE + r] = val.z;
        At[(4 * c + 3) * AT_STRIDE + r] = val.w;
    }
    __syncthreads();

    int tx = tid & 15, ty = tid >> 4;   // tx: 8-col group, ty: 8-node group

    unsigned long long acc[8][4];
#pragma unroll
    for (int i = 0; i < 8; i++)
#pragma unroll
        for (int jj = 0; jj < 4; jj++) acc[i][jj] = 0ull;

#pragma unroll 4
    for (int k = 0; k < H; k++) {
        const float* atk = At + k * AT_STRIDE + ty * 8;
        float4 a0 = *(const float4*)(atk);
        float4 a1 = *(const float4*)(atk + 4);
        const float* wk = Ws + k * H + tx * 8;
        ulonglong2 wlo = *(const ulonglong2*)(wk);
        ulonglong2 whi = *(const ulonglong2*)(wk + 4);
        float av[8] = {a0.x, a0.y, a0.z, a0.w, a1.x, a1.y, a1.z, a1.w};
        unsigned long long wv[4] = {wlo.x, wlo.y, whi.x, whi.y};
#pragma unroll
        for (int i = 0; i < 8; i++) {
            unsigned long long ap;
            asm("mov.b64 %0, {%1, %1};" : "=l"(ap) : "f"(av[i]));
#pragma unroll
            for (int jj = 0; jj < 4; jj++)
                asm("fma.rn.f32x2 %0, %1, %2, %0;"
                    : "+l"(acc[i][jj]) : "l"(ap), "l"(wv[jj]));
        }
    }

#pragma unroll
    for (int i = 0; i < 8; i++) {
        int gn = nb + ty * 8 + i;
        if (gn >= n) continue;
        float v[8];
#pragma unroll
        for (int jj = 0; jj < 4; jj++) {
            float lo, hi;
            asm("mov.b64 {%0, %1}, %2;" : "=f"(lo), "=f"(hi) : "l"(acc[i][jj]));
            v[2 * jj] = lo;
            v[2 * jj + 1] = hi;
        }
        int cb = tx * 8;
#pragma unroll
        for (int jj = 0; jj < 8; jj++) {
            float x = v[jj];
            if (BIAS) x += bs[cb + jj];
            if (DOSSP) x = sspf(x);
            v[jj] = x;
        }
        if (RES) {
            float4 r0 = ((const float4*)res)[(size_t)gn * 32 + tx * 2];
            float4 r1 = ((const float4*)res)[(size_t)gn * 32 + tx * 2 + 1];
            v[0] += r0.x; v[1] += r0.y; v[2] += r0.z; v[3] += r0.w;
            v[4] += r1.x; v[5] += r1.y; v[6] += r1.z; v[7] += r1.w;
        }
        ((float4*)out)[(size_t)gn * 32 + tx * 2]     = make_float4(v[0], v[1], v[2], v[3]);
        ((float4*)out)[(size_t)gn * 32 + tx * 2 + 1] = make_float4(v[4], v[5], v[6], v[7]);
    }
}

// ---------------- readout: out = hbuf @ u_l2_w + u_l2_b ----------------
__global__ void __launch_bounds__(256) readout_kernel(const float* __restrict__ hbuf,
                                                      const float* __restrict__ w2,
                                                      const float* __restrict__ b2,
                                                      float* __restrict__ out) {
    __shared__ float ws[H * 3];
    int tid = threadIdx.x;
    for (int idx = tid; idx < H * 3; idx += 256) ws[idx] = w2[idx];
    __syncthreads();

    int g = blockIdx.x * 256 + tid;
    int node = g >> 5;
    if (node >= N_NODES) return;
    int lane = g & 31;

    float4 h = ((const float4*)hbuf)[node * 32 + lane];
    int k0 = lane * 4;
    float s0 = h.x * ws[k0 * 3 + 0] + h.y * ws[(k0 + 1) * 3 + 0] +
               h.z * ws[(k0 + 2) * 3 + 0] + h.w * ws[(k0 + 3) * 3 + 0];
    float s1 = h.x * ws[k0 * 3 + 1] + h.y * ws[(k0 + 1) * 3 + 1] +
               h.z * ws[(k0 + 2) * 3 + 1] + h.w * ws[(k0 + 3) * 3 + 1];
    float s2 = h.x * ws[k0 * 3 + 2] + h.y * ws[(k0 + 1) * 3 + 2] +
               h.z * ws[(k0 + 2) * 3 + 2] + h.w * ws[(k0 + 3) * 3 + 2];
#pragma unroll
    for (int off = 16; off; off >>= 1) {
        s0 += __shfl_down_sync(0xffffffffu, s0, off);
        s1 += __shfl_down_sync(0xffffffffu, s1, off);
        s2 += __shfl_down_sync(0xffffffffu, s2, off);
    }
    if (lane == 0) {
        out[node * 3 + 0] = s0 + b2[0];
        out[node * 3 + 1] = s1 + b2[1];
        out[node * 3 + 2] = s2 + b2[2];
    }
}

// ---------------- launch ----------------
static const int GEMM_SMEM = (H * H + H * AT_STRIDE) * sizeof(float);

extern "C" void kernel_launch(void* const* d_in, const int* in_sizes, int n_in,
                              void* d_out, int out_size) {
    const float* z        = (const float*)d_in[0];
    const float* dist     = (const float*)d_in[1];
    const int*   ei       = (const int*)d_in[2];
    const float* init_w   = (const float*)d_in[3];
    const float* init_b   = (const float*)d_in[4];
    const float* e_lin_w[2] = {(const float*)d_in[5],  (const float*)d_in[14]};
    const float* e_m0_w[2]  = {(const float*)d_in[6],  (const float*)d_in[15]};
    const float* e_m0_b[2]  = {(const float*)d_in[7],  (const float*)d_in[16]};
    const float* e_m2_w[2]  = {(const float*)d_in[8],  (const float*)d_in[17]};
    const float* e_m2_b[2]  = {(const float*)d_in[9],  (const float*)d_in[18]};
    const float* v_l1_w[2]  = {(const float*)d_in[10], (const float*)d_in[19]};
    const float* v_l1_b[2]  = {(const float*)d_in[11], (const float*)d_in[20]};
    const float* v_l2_w[2]  = {(const float*)d_in[12], (const float*)d_in[21]};
    const float* v_l2_b[2]  = {(const float*)d_in[13], (const float*)d_in[22]};
    const float* u_l1_w   = (const float*)d_in[23];
    const float* u_l1_b   = (const float*)d_in[24];
    const float* u_l2_w   = (const float*)d_in[25];
    const float* u_l2_b   = (const float*)d_in[26];
    float* out = (float*)d_out;

    float *v, *vlin, *agg, *hbuf, *wtab, *cs;
    int *cnt, *off, *pos, *bsum, *jt;
    cudaGetSymbolAddress((void**)&v,    g_v);
    cudaGetSymbolAddress((void**)&vlin, g_vlin);
    cudaGetSymbolAddress((void**)&agg,  g_agg);
    cudaGetSymbolAddress((void**)&hbuf, g_hbuf);
    cudaGetSymbolAddress((void**)&wtab, g_wtab);
    cudaGetSymbolAddress((void**)&cnt,  g_cnt);
    cudaGetSymbolAddress((void**)&off,  g_off);
    cudaGetSymbolAddress((void**)&pos,  g_pos);
    cudaGetSymbolAddress((void**)&bsum, g_bsum);
    cudaGetSymbolAddress((void**)&jt,   g_jt);
    cudaGetSymbolAddress((void**)&cs,   g_cs);

    cudaFuncSetAttribute((const void*)gemm128<false, false, false>,
                         cudaFuncAttributeMaxDynamicSharedMemorySize, GEMM_SMEM);
    cudaFuncSetAttribute((const void*)gemm128<true, true, false>,
                         cudaFuncAttributeMaxDynamicSharedMemorySize, GEMM_SMEM);
    cudaFuncSetAttribute((const void*)gemm128<true, false, true>,
                         cudaFuncAttributeMaxDynamicSharedMemorySize, GEMM_SMEM);

    const int gemm_grid = (N_NODES + 127) / 128;
    const int egrid = (N_EDGES + 255) / 256;
    const int ngrid = (N_NODES + 255) / 256;

    table_kernel<<<2 * NBINS, H>>>(e_m0_w[0], e_m0_b[0], e_m2_w[0], e_m2_b[0],
                                   e_m0_w[1], e_m0_b[1], e_m2_w[1], e_m2_b[1], wtab);
    init_kernel<<<(N_NODES * 32 + 255) / 256, 256>>>(z, init_w, init_b, v);

    // CSR build (shared by both layers)
    zero_cnt_kernel<<<ngrid, 256>>>(cnt);
    hist_kernel<<<egrid, 256>>>(ei, cnt);
    scan1_kernel<<<SCAN_BLOCKS, 256>>>(cnt, off, bsum);
    scan2_kernel<<<1, 256>>>(bsum);
    scan3_kernel<<<SCAN_BLOCKS, 256>>>(off, bsum, pos);
    scatter_kernel<<<egrid, 256>>>(ei, dist, pos, jt, cs);

    for (int l = 0; l < 2; l++) {
        gemm128<false, false, false><<<gemm_grid, 256, GEMM_SMEM>>>(
            v, e_lin_w[l], nullptr, nullptr, vlin, N_NODES);
        agg_kernel<<<(N_NODES + 7) / 8, 256>>>(vlin, off, jt, cs,
                                               wtab + l * NBINS * H, agg);
        gemm128<true, true, false><<<gemm_grid, 256, GEMM_SMEM>>>(
            agg, v_l1_w[l], v_l1_b[l], nullptr, hbuf, N_NODES);
        gemm128<true, false, true><<<gemm_grid, 256, GEMM_SMEM>>>(
            hbuf, v_l2_w[l], v_l2_b[l], v, v, N_NODES);
    }

    gemm128<true, true, false><<<gemm_grid, 256, GEMM_SMEM>>>(
        v, u_l1_w, u_l1_b, nullptr, hbuf, N_NODES);
    readout_kernel<<<(N_NODES * 32 + 255) / 256, 256>>>(hbuf, u_l2_w, u_l2_b, out);
}

// round 4
// speedup vs baseline: 1.3204x; 1.0184x over previous
#include <cuda_runtime.h>
#include <math.h>

#define N_NODES 50000
#define N_EDGES 800000
#define H 128
#define G_RBF 50
#define NBINS 7
#define CUTOFF 6.0f
#define SSP_SHIFT 0.6931471805599453f
#define PI_F 3.14159265358979323846f

#define SCAN_BLOCKS ((N_NODES + 255) / 256)   // 196
#define AT_STRIDE 132   // 128 + 4 pad (floats), rows stay 16B-aligned

// ---------------- scratch (no allocation allowed) ----------------
__device__ float g_v[N_NODES * H];
__device__ float g_vlin[N_NODES * H];
__device__ float g_agg[N_NODES * H];
__device__ float g_wtab[2 * NBINS * H];
// CSR scratch
__device__ int   g_cnt[N_NODES];
__device__ int   g_off[N_NODES + 1];
__device__ int   g_pos[N_NODES];
__device__ int   g_bsum[SCAN_BLOCKS];
__device__ int   g_jt[N_EDGES];     // j | (tbin << 27)
__device__ float g_cs[N_EDGES];     // cutoff gate C

__device__ __forceinline__ float sspf(float x) {
    return fmaxf(x, 0.0f) + log1pf(expf(-fabsf(x))) - SSP_SHIFT;
}

// ---------------- filter table: T[layer][tbin][h] ----------------
__global__ void table_kernel(const float* __restrict__ m0w0, const float* __restrict__ m0b0,
                             const float* __restrict__ m2w0, const float* __restrict__ m2b0,
                             const float* __restrict__ m0w1, const float* __restrict__ m0b1,
                             const float* __restrict__ m2w1, const float* __restrict__ m2b1,
                             float* __restrict__ wtab) {
    int l = blockIdx.x / NBINS;
    int t = blockIdx.x % NBINS;
    const float* m0w = l ? m0w1 : m0w0;
    const float* m0b = l ? m0b1 : m0b0;
    const float* m2w = l ? m2w1 : m2w0;
    const float* m2b = l ? m2b1 : m2b0;

    __shared__ float hs[H];
    int h = threadIdx.x;

    const float step = CUTOFF / (float)(G_RBF - 1);
    const float coeff = -0.5f / (step * step);
    float acc = m0b[h];
#pragma unroll 10
    for (int g = 0; g < G_RBF; g++) {
        float off = step * (float)g;
        float dd = (float)t - off;
        acc += expf(coeff * dd * dd) * m0w[g * H + h];
    }
    hs[h] = sspf(acc);
    __syncthreads();

    float o = m2b[h];
#pragma unroll 16
    for (int k = 0; k < H; k++) o += hs[k] * m2w[k * H + h];
    wtab[(l * NBINS + t) * H + h] = o;
}

// ---------------- init: v = z @ init_w + init_b ----------------
__global__ void init_kernel(const float* __restrict__ z, const float* __restrict__ iw,
                            const float* __restrict__ ib, float* __restrict__ v) {
    int g = blockIdx.x * blockDim.x + threadIdx.x;
    if (g >= N_NODES * 32) return;
    int n = g >> 5, c4 = g & 31;
    float4 b = ((const float4*)ib)[c4];
    float z0 = z[n * 3 + 0], z1 = z[n * 3 + 1], z2 = z[n * 3 + 2];
    float4 w0 = ((const float4*)iw)[c4];
    float4 w1 = ((const float4*)iw)[32 + c4];
    float4 w2 = ((const float4*)iw)[64 + c4];
    float4 o;
    o.x = b.x + z0 * w0.x + z1 * w1.x + z2 * w2.x;
    o.y = b.y + z0 * w0.y + z1 * w1.y + z2 * w2.y;
    o.z = b.z + z0 * w0.z + z1 * w1.z + z2 * w2.z;
    o.w = b.w + z0 * w0.w + z1 * w1.w + z2 * w2.w;
    ((float4*)v)[n * 32 + c4] = o;
}

// ---------------- CSR build ----------------
__global__ void zero_cnt_kernel(int* __restrict__ cnt) {
    int i = blockIdx.x * blockDim.x + threadIdx.x;
    if (i < N_NODES) cnt[i] = 0;
}

__global__ void hist_kernel(const int* __restrict__ ei, int* __restrict__ cnt) {
    int e = blockIdx.x * blockDim.x + threadIdx.x;
    if (e < N_EDGES) atomicAdd(&cnt[ei[N_EDGES + e]], 1);
}

__global__ void scan1_kernel(const int* __restrict__ cnt, int* __restrict__ off,
                             int* __restrict__ bsum) {
    __shared__ int s[256];
    int t = threadIdx.x;
    int i = blockIdx.x * 256 + t;
    int v = (i < N_NODES) ? cnt[i] : 0;
    s[t] = v;
    __syncthreads();
#pragma unroll
    for (int o = 1; o < 256; o <<= 1) {
        int x = (t >= o) ? s[t - o] : 0;
        __syncthreads();
        s[t] += x;
        __syncthreads();
    }
    if (i < N_NODES) off[i] = s[t] - v;  // exclusive within block
    if (t == 255) bsum[blockIdx.x] = s[255];
}

__global__ void scan2_kernel(int* __restrict__ bsum) {
    __shared__ int s[256];
    int t = threadIdx.x;
    int v = (t < SCAN_BLOCKS) ? bsum[t] : 0;
    s[t] = v;
    __syncthreads();
#pragma unroll
    for (int o = 1; o < 256; o <<= 1) {
        int x = (t >= o) ? s[t - o] : 0;
        __syncthreads();
        s[t] += x;
        __syncthreads();
    }
    if (t < SCAN_BLOCKS) bsum[t] = s[t] - v;  // exclusive
}

__global__ void scan3_kernel(int* __restrict__ off, const int* __restrict__ bsum,
                             int* __restrict__ pos) {
    int i = blockIdx.x * blockDim.x + threadIdx.x;
    if (i < N_NODES) {
        int o = off[i] + bsum[i >> 8];
        off[i] = o;
        pos[i] = o;
    }
    if (i == 0) off[N_NODES] = N_EDGES;
}

__global__ void scatter_kernel(const int* __restrict__ ei, const float* __restrict__ dist,
                               int* __restrict__ pos, int* __restrict__ jt,
                               float* __restrict__ cs) {
    int e = blockIdx.x * blockDim.x + threadIdx.x;
    if (e >= N_EDGES) return;
    int j = ei[e];
    int i = ei[N_EDGES + e];
    float d = dist[e];
    int tb = (int)d;
    if (tb > NBINS - 1) tb = NBINS - 1;
    float C = 0.5f * cosf(d * (PI_F / CUTOFF)) + 0.5f;
    int p = atomicAdd(&pos[i], 1);
    jt[p] = j | (tb << 27);
    cs[p] = C;
}

// ---------------- aggregate: agg[i] = sum_{e->i} vlin[j]*T[tb]*C ----------------
// warp per node, no atomics, 4-edge software pipeline for MLP
__global__ void __launch_bounds__(256) agg_kernel(const float* __restrict__ vlin,
                                                  const int* __restrict__ off,
                                                  const int* __restrict__ jt,
                                                  const float* __restrict__ cs,
                                                  const float* __restrict__ wtab,
                                                  float* __restrict__ agg) {
    __shared__ float4 ws[NBINS * 32];
    int tid = threadIdx.x;
    if (tid < NBINS * 32) ws[tid] = ((const float4*)wtab)[tid];
    __syncthreads();

    int node = blockIdx.x * 8 + (tid >> 5);
    if (node >= N_NODES) return;
    int lane = tid & 31;

    int s = off[node], e = off[node + 1];
    float4 acc = make_float4(0.f, 0.f, 0.f, 0.f);
    const float4* vlin4 = (const float4*)vlin;

    for (int base = s; base < e; base += 32) {
        int m = min(32, e - base);
        int mj = (lane < m) ? jt[base + lane] : 0;
        float mc = (lane < m) ? cs[base + lane] : 0.f;
        int t = 0;
        for (; t + 4 <= m; t += 4) {
            int jv0 = __shfl_sync(0xffffffffu, mj, t);
            int jv1 = __shfl_sync(0xffffffffu, mj, t + 1);
            int jv2 = __shfl_sync(0xffffffffu, mj, t + 2);
            int jv3 = __shfl_sync(0xffffffffu, mj, t + 3);
            float c0 = __shfl_sync(0xffffffffu, mc, t);
            float c1 = __shfl_sync(0xffffffffu, mc, t + 1);
            float c2 = __shfl_sync(0xffffffffu, mc, t + 2);
            float c3 = __shfl_sync(0xffffffffu, mc, t + 3);
            float4 x0 = __ldg(vlin4 + (size_t)(jv0 & 0x07FFFFFF) * 32 + lane);
            float4 x1 = __ldg(vlin4 + (size_t)(jv1 & 0x07FFFFFF) * 32 + lane);
            float4 x2 = __ldg(vlin4 + (size_t)(jv2 & 0x07FFFFFF) * 32 + lane);
            float4 x3 = __ldg(vlin4 + (size_t)(jv3 & 0x07FFFFFF) * 32 + lane);
            float4 w0 = ws[(jv0 >> 27) * 32 + lane];
            float4 w1 = ws[(jv1 >> 27) * 32 + lane];
            float4 w2 = ws[(jv2 >> 27) * 32 + lane];
            float4 w3 = ws[(jv3 >> 27) * 32 + lane];
            acc.x += x0.x * w0.x * c0; acc.y += x0.y * w0.y * c0;
            acc.z += x0.z * w0.z * c0; acc.w += x0.w * w0.w * c0;
            acc.x += x1.x * w1.x * c1; acc.y += x1.y * w1.y * c1;
            acc.z += x1.z * w1.z * c1; acc.w += x1.w * w1.w * c1;
            acc.x += x2.x * w2.x * c2; acc.y += x2.y * w2.y * c2;
            acc.z += x2.z * w2.z * c2; acc.w += x2.w * w2.w * c2;
            acc.x += x3.x * w3.x * c3; acc.y += x3.y * w3.y * c3;
            acc.z += x3.z * w3.z * c3; acc.w += x3.w * w3.w * c3;
        }
        for (; t < m; t++) {
            int jv = __shfl_sync(0xffffffffu, mj, t);
            float c = __shfl_sync(0xffffffffu, mc, t);
            float4 x = __ldg(vlin4 + (size_t)(jv & 0x07FFFFFF) * 32 + lane);
            float4 w = ws[(jv >> 27) * 32 + lane];
            acc.x += x.x * w.x * c;
            acc.y += x.y * w.y * c;
            acc.z += x.z * w.z * c;
            acc.w += x.w * w.w * c;
        }
    }
    ((float4*)agg)[(size_t)node * 32 + lane] = acc;
}

// ---------------- FFMA2 inner product core ----------------
// acc (8 nodes x 4 col-pairs) += At[k][node-block] x Ws[k][col-block]
__device__ __forceinline__ void mm_core(const float* At, const float* Ws,
                                        int tx, int ty, unsigned long long acc[8][4]) {
#pragma unroll 4
    for (int k = 0; k < H; k++) {
        const float* atk = At + k * AT_STRIDE + ty * 8;
        float4 a0 = *(const float4*)(atk);
        float4 a1 = *(const float4*)(atk + 4);
        const float* wk = Ws + k * H + tx * 8;
        ulonglong2 wlo = *(const ulonglong2*)(wk);
        ulonglong2 whi = *(const ulonglong2*)(wk + 4);
        float av[8] = {a0.x, a0.y, a0.z, a0.w, a1.x, a1.y, a1.z, a1.w};
        unsigned long long wv[4] = {wlo.x, wlo.y, whi.x, whi.y};
#pragma unroll
        for (int i = 0; i < 8; i++) {
            unsigned long long ap;
            asm("mov.b64 %0, {%1, %1};" : "=l"(ap) : "f"(av[i]));
#pragma unroll
            for (int jj = 0; jj < 4; jj++)
                asm("fma.rn.f32x2 %0, %1, %2, %0;"
                    : "+l"(acc[i][jj]) : "l"(ap), "l"(wv[jj]));
        }
    }
}

__device__ __forceinline__ void unpack8(const unsigned long long a[4], float v[8]) {
#pragma unroll
    for (int jj = 0; jj < 4; jj++) {
        float lo, hi;
        asm("mov.b64 {%0, %1}, %2;" : "=f"(lo), "=f"(hi) : "l"(a[jj]));
        v[2 * jj] = lo;
        v[2 * jj + 1] = hi;
    }
}

// ---------------- plain GEMM: out = A @ W (for vlin) ----------------
__global__ void __launch_bounds__(256) gemm_plain(const float* __restrict__ A,
                                                  const float* __restrict__ W,
                                                  float* __restrict__ out, int n) {
    extern __shared__ float sm[];
    float* Ws = sm;
    float* At = sm + H * H;

    int tid = threadIdx.x;
    for (int idx = tid; idx < (H * H) / 4; idx += 256)
        ((float4*)Ws)[idx] = ((const float4*)W)[idx];

    int nb = blockIdx.x * 128;
    for (int idx = tid; idx < 128 * 32; idx += 256) {
        int r = idx & 127, c = idx >> 7;
        int gn = nb + r;
        float4 val = (gn < n) ? ((const float4*)A)[(size_t)gn * 32 + c]
                              : make_float4(0.f, 0.f, 0.f, 0.f);
        At[(4 * c + 0) * AT_STRIDE + r] = val.x;
        At[(4 * c + 1) * AT_STRIDE + r] = val.y;
        At[(4 * c + 2) * AT_STRIDE + r] = val.z;
        At[(4 * c + 3) * AT_STRIDE + r] = val.w;
    }
    __syncthreads();

    int tx = tid & 15, ty = tid >> 4;
    unsigned long long acc[8][4];
#pragma unroll
    for (int i = 0; i < 8; i++)
#pragma unroll
        for (int jj = 0; jj < 4; jj++) acc[i][jj] = 0ull;

    mm_core(At, Ws, tx, ty, acc);

#pragma unroll
    for (int i = 0; i < 8; i++) {
        int gn = nb + ty * 8 + i;
        if (gn >= n) continue;
        float v[8];
        unpack8(acc[i], v);
        ((float4*)out)[(size_t)gn * 32 + tx * 2]     = make_float4(v[0], v[1], v[2], v[3]);
        ((float4*)out)[(size_t)gn * 32 + tx * 2 + 1] = make_float4(v[4], v[5], v[6], v[7]);
    }
}

// ---------------- fused node MLP: v += ssp(agg@W1+b1)@W2 + b2 ----------------
__global__ void __launch_bounds__(256) fused_mlp(const float* __restrict__ A,
                                                 const float* __restrict__ W1,
                                                 const float* __restrict__ b1,
                                                 const float* __restrict__ W2,
                                                 const float* __restrict__ b2,
                                                 float* __restrict__ v, int n) {
    extern __shared__ float sm[];
    float* Ws = sm;
    float* At = sm + H * H;
    __shared__ float bs1[H], bs2[H];

    int tid = threadIdx.x;
    for (int idx = tid; idx < (H * H) / 4; idx += 256)
        ((float4*)Ws)[idx] = ((const float4*)W1)[idx];
    if (tid < H) { bs1[tid] = b1[tid]; bs2[tid] = b2[tid]; }

    int nb = blockIdx.x * 128;
    for (int idx = tid; idx < 128 * 32; idx += 256) {
        int r = idx & 127, c = idx >> 7;
        int gn = nb + r;
        float4 val = (gn < n) ? ((const float4*)A)[(size_t)gn * 32 + c]
                              : make_float4(0.f, 0.f, 0.f, 0.f);
        At[(4 * c + 0) * AT_STRIDE + r] = val.x;
        At[(4 * c + 1) * AT_STRIDE + r] = val.y;
        At[(4 * c + 2) * AT_STRIDE + r] = val.z;
        At[(4 * c + 3) * AT_STRIDE + r] = val.w;
    }
    __syncthreads();

    int tx = tid & 15, ty = tid >> 4;
    unsigned long long acc[8][4];
#pragma unroll
    for (int i = 0; i < 8; i++)
#pragma unroll
        for (int jj = 0; jj < 4; jj++) acc[i][jj] = 0ull;

    mm_core(At, Ws, tx, ty, acc);
    __syncthreads();   // everyone done reading At/Ws

    // t1 = ssp(acc + b1) -> back into At (transposed: At[col][node])
#pragma unroll
    for (int i = 0; i < 8; i++) {
        float t1[8];
        unpack8(acc[i], t1);
        int node = ty * 8 + i;
#pragma unroll
        for (int jj = 0; jj < 8; jj++) {
            int col = tx * 8 + jj;
            At[col * AT_STRIDE + node] = sspf(t1[jj] + bs1[col]);
        }
    }
    // stage W2
    for (int idx = tid; idx < (H * H) / 4; idx += 256)
        ((float4*)Ws)[idx] = ((const float4*)W2)[idx];
    __syncthreads();

#pragma unroll
    for (int i = 0; i < 8; i++)
#pragma unroll
        for (int jj = 0; jj < 4; jj++) acc[i][jj] = 0ull;

    mm_core(At, Ws, tx, ty, acc);

#pragma unroll
    for (int i = 0; i < 8; i++) {
        int gn = nb + ty * 8 + i;
        if (gn >= n) continue;
        float o[8];
        unpack8(acc[i], o);
        int cb = tx * 8;
        float4 r0 = ((const float4*)v)[(size_t)gn * 32 + tx * 2];
        float4 r1 = ((const float4*)v)[(size_t)gn * 32 + tx * 2 + 1];
        o[0] += bs2[cb + 0] + r0.x; o[1] += bs2[cb + 1] + r0.y;
        o[2] += bs2[cb + 2] + r0.z; o[3] += bs2[cb + 3] + r0.w;
        o[4] += bs2[cb + 4] + r1.x; o[5] += bs2[cb + 5] + r1.y;
        o[6] += bs2[cb + 6] + r1.z; o[7] += bs2[cb + 7] + r1.w;
        ((float4*)v)[(size_t)gn * 32 + tx * 2]     = make_float4(o[0], o[1], o[2], o[3]);
        ((float4*)v)[(size_t)gn * 32 + tx * 2 + 1] = make_float4(o[4], o[5], o[6], o[7]);
    }
}

// ---------------- fused readout: out = ssp(v@u1+b1) @ u2 + b2  ([N,3]) ----------------
__global__ void __launch_bounds__(256) fused_readout(const float* __restrict__ A,
                                                     const float* __restrict__ W1,
                                                     const float* __restrict__ b1,
                                                     const float* __restrict__ W2,
                                                     const float* __restrict__ b2,
                                                     float* __restrict__ out, int n) {
    extern __shared__ float sm[];
    float* Ws = sm;
    float* At = sm + H * H;
    __shared__ float bs1[H], ws2[H * 3];

    int tid = threadIdx.x;
    for (int idx = tid; idx < (H * H) / 4; idx += 256)
        ((float4*)Ws)[idx] = ((const float4*)W1)[idx];
    if (tid < H) bs1[tid] = b1[tid];
    for (int idx = tid; idx < H * 3; idx += 256) ws2[idx] = W2[idx];

    int nb = blockIdx.x * 128;
    for (int idx = tid; idx < 128 * 32; idx += 256) {
        int r = idx & 127, c = idx >> 7;
        int gn = nb + r;
        float4 val = (gn < n) ? ((const float4*)A)[(size_t)gn * 32 + c]
                              : make_float4(0.f, 0.f, 0.f, 0.f);
        At[(4 * c + 0) * AT_STRIDE + r] = val.x;
        At[(4 * c + 1) * AT_STRIDE + r] = val.y;
        At[(4 * c + 2) * AT_STRIDE + r] = val.z;
        At[(4 * c + 3) * AT_STRIDE + r] = val.w;
    }
    __syncthreads();

    int tx = tid & 15, ty = tid >> 4;
    unsigned long long acc[8][4];
#pragma unroll
    for (int i = 0; i < 8; i++)
#pragma unroll
        for (int jj = 0; jj < 4; jj++) acc[i][jj] = 0ull;

    mm_core(At, Ws, tx, ty, acc);

    // preload this thread's 8x3 slice of u2
    float u2loc[8][3];
#pragma unroll
    for (int jj = 0; jj < 8; jj++) {
        int col = tx * 8 + jj;
        u2loc[jj][0] = ws2[col * 3 + 0];
        u2loc[jj][1] = ws2[col * 3 + 1];
        u2loc[jj][2] = ws2[col * 3 + 2];
    }

#pragma unroll
    for (int i = 0; i < 8; i++) {
        float h[8];
        unpack8(acc[i], h);
        float p0 = 0.f, p1 = 0.f, p2 = 0.f;
        int cb = tx * 8;
#pragma unroll
        for (int jj = 0; jj < 8; jj++) {
            float x = sspf(h[jj] + bs1[cb + jj]);
            p0 += x * u2loc[jj][0];
            p1 += x * u2loc[jj][1];
            p2 += x * u2loc[jj][2];
        }
        // reduce across the 16 tx lanes (width-16 shuffle)
#pragma unroll
        for (int off = 8; off; off >>= 1) {
            p0 += __shfl_down_sync(0xffffffffu, p0, off, 16);
            p1 += __shfl_down_sync(0xffffffffu, p1, off, 16);
            p2 += __shfl_down_sync(0xffffffffu, p2, off, 16);
        }
        if (tx == 0) {
            int gn = nb + ty * 8 + i;
            if (gn < n) {
                out[gn * 3 + 0] = p0 + b2[0];
                out[gn * 3 + 1] = p1 + b2[1];
                out[gn * 3 + 2] = p2 + b2[2];
            }
        }
    }
}

// ---------------- launch ----------------
static const int GEMM_SMEM = (H * H + H * AT_STRIDE) * sizeof(float);

extern "C" void kernel_launch(void* const* d_in, const int* in_sizes, int n_in,
                              void* d_out, int out_size) {
    const float* z        = (const float*)d_in[0];
    const float* dist     = (const float*)d_in[1];
    const int*   ei       = (const int*)d_in[2];
    const float* init_w   = (const float*)d_in[3];
    const float* init_b   = (const float*)d_in[4];
    const float* e_lin_w[2] = {(const float*)d_in[5],  (const float*)d_in[14]};
    const float* e_m0_w[2]  = {(const float*)d_in[6],  (const float*)d_in[15]};
    const float* e_m0_b[2]  = {(const float*)d_in[7],  (const float*)d_in[16]};
    const float* e_m2_w[2]  = {(const float*)d_in[8],  (const float*)d_in[17]};
    const float* e_m2_b[2]  = {(const float*)d_in[9],  (const float*)d_in[18]};
    const float* v_l1_w[2]  = {(const float*)d_in[10], (const float*)d_in[19]};
    const float* v_l1_b[2]  = {(const float*)d_in[11], (const float*)d_in[20]};
    const float* v_l2_w[2]  = {(const float*)d_in[12], (const float*)d_in[21]};
    const float* v_l2_b[2]  = {(const float*)d_in[13], (const float*)d_in[22]};
    const float* u_l1_w   = (const float*)d_in[23];
    const float* u_l1_b   = (const float*)d_in[24];
    const float* u_l2_w   = (const float*)d_in[25];
    const float* u_l2_b   = (const float*)d_in[26];
    float* out = (float*)d_out;

    float *v, *vlin, *agg, *wtab, *cs;
    int *cnt, *off, *pos, *bsum, *jt;
    cudaGetSymbolAddress((void**)&v,    g_v);
    cudaGetSymbolAddress((void**)&vlin, g_vlin);
    cudaGetSymbolAddress((void**)&agg,  g_agg);
    cudaGetSymbolAddress((void**)&wtab, g_wtab);
    cudaGetSymbolAddress((void**)&cnt,  g_cnt);
    cudaGetSymbolAddress((void**)&off,  g_off);
    cudaGetSymbolAddress((void**)&pos,  g_pos);
    cudaGetSymbolAddress((void**)&bsum, g_bsum);
    cudaGetSymbolAddress((void**)&jt,   g_jt);
    cudaGetSymbolAddress((void**)&cs,   g_cs);

    cudaFuncSetAttribute((const void*)gemm_plain,
                         cudaFuncAttributeMaxDynamicSharedMemorySize, GEMM_SMEM);
    cudaFuncSetAttribute((const void*)fused_mlp,
                         cudaFuncAttributeMaxDynamicSharedMemorySize, GEMM_SMEM);
    cudaFuncSetAttribute((const void*)fused_readout,
                         cudaFuncAttributeMaxDynamicSharedMemorySize, GEMM_SMEM);

    const int gemm_grid = (N_NODES + 127) / 128;
    const int egrid = (N_EDGES + 255) / 256;
    const int ngrid = (N_NODES + 255) / 256;

    // launch order arranged so ncu (-s 5) profiles the first big GEMM
    table_kernel<<<2 * NBINS, H>>>(e_m0_w[0], e_m0_b[0], e_m2_w[0], e_m2_b[0],   // 0
                                   e_m0_w[1], e_m0_b[1], e_m2_w[1], e_m2_b[1], wtab);
    init_kernel<<<(N_NODES * 32 + 255) / 256, 256>>>(z, init_w, init_b, v);      // 1
    zero_cnt_kernel<<<ngrid, 256>>>(cnt);                                        // 2
    hist_kernel<<<egrid, 256>>>(ei, cnt);                                        // 3
    scan1_kernel<<<SCAN_BLOCKS, 256>>>(cnt, off, bsum);                          // 4
    gemm_plain<<<gemm_grid, 256, GEMM_SMEM>>>(v, e_lin_w[0], vlin, N_NODES);     // 5 <- profiled
    scan2_kernel<<<1, 256>>>(bsum);                                              // 6
    scan3_kernel<<<SCAN_BLOCKS, 256>>>(off, bsum, pos);                          // 7
    scatter_kernel<<<egrid, 256>>>(ei, dist, pos, jt, cs);                       // 8

    // layer 0
    agg_kernel<<<(N_NODES + 7) / 8, 256>>>(vlin, off, jt, cs, wtab, agg);
    fused_mlp<<<gemm_grid, 256, GEMM_SMEM>>>(agg, v_l1_w[0], v_l1_b[0],
                                             v_l2_w[0], v_l2_b[0], v, N_NODES);
    // layer 1
    gemm_plain<<<gemm_grid, 256, GEMM_SMEM>>>(v, e_lin_w[1], vlin, N_NODES);
    agg_kernel<<<(N_NODES + 7) / 8, 256>>>(vlin, off, jt, cs, wtab + NBINS * H, agg);
    fused_mlp<<<gemm_grid, 256, GEMM_SMEM>>>(agg, v_l1_w[1], v_l1_b[1],
                                             v_l2_w[1], v_l2_b[1], v, N_NODES);
    // readout
    fused_readout<<<gemm_grid, 256, GEMM_SMEM>>>(v, u_l1_w, u_l1_b,
                                                 u_l2_w, u_l2_b, out, N_NODES);
}